// round 11
// baseline (speedup 1.0000x reference)
#include <cuda_runtime.h>
#include <cstdint>

#define N_NODES 50000
#define N_EDGES 800000
#define IN_DIM  256
#define HIDDEN  128
#define OUT_DIM 64
#define NEG_SLOPE 0.1f

// Scratch (device globals: allocation-free rule)
__device__ __align__(16) float g_h0[N_NODES * HIDDEN];  // activations
__device__ __align__(16) float g_h1[N_NODES * HIDDEN];  // transformed feats (prescaled)
__device__ float g_dinv[N_NODES];
__device__ int   g_cnt[N_NODES];
__device__ int   g_fill[N_NODES];
__device__ int   g_rowptr[N_NODES + 1];
__device__ int   g_srcidx[N_EDGES];
__device__ int   g_is64;

#define BUF_EXT 0
#define BUF_H0  1

// ---------------------------------------------------------------------------
// tf32 helpers (3xTF32 split: D = Ah*Bh + Ah*Bl + Al*Bh, fp32 accumulate)
// ---------------------------------------------------------------------------
__device__ __forceinline__ uint32_t f2tf32(float x) {
    uint32_t u;
    asm("cvt.rna.tf32.f32 %0, %1;" : "=r"(u) : "f"(x));
    return u;
}

#define MMA_TF32(D, a, b) \
    asm volatile("mma.sync.aligned.m16n8k8.row.col.f32.tf32.tf32.f32 " \
        "{%0,%1,%2,%3}, {%4,%5,%6,%7}, {%8,%9}, {%0,%1,%2,%3};" \
        : "+f"((D)[0]), "+f"((D)[1]), "+f"((D)[2]), "+f"((D)[3]) \
        : "r"((a).x), "r"((a).y), "r"((a).z), "r"((a).w), "r"((b).x), "r"((b).y))

// ---------------------------------------------------------------------------
// Init + dtype detection
// ---------------------------------------------------------------------------
__global__ void k_init() {
    int i = blockIdx.x * blockDim.x + threadIdx.x;
    if (i < N_NODES) { g_cnt[i] = 0; g_fill[i] = 0; }
    if (i == 0) g_is64 = 1;
}
// int64 edge_index with values < 50000 => every odd 32-bit word is zero.
__global__ void k_detect(const unsigned* __restrict__ e) {
    int i = blockIdx.x * blockDim.x + threadIdx.x;
    if (i < 4096) { if (e[2 * i + 1] != 0u) g_is64 = 0; }
}
__device__ __forceinline__ int edge_src(const void* ei, int e) {
    return g_is64 ? (int)((const long long*)ei)[e] : ((const int*)ei)[e];
}
__device__ __forceinline__ int edge_dst(const void* ei, int e) {
    return g_is64 ? (int)((const long long*)ei)[N_EDGES + e] : ((const int*)ei)[N_EDGES + e];
}

// ---------------------------------------------------------------------------
// CSR build
// ---------------------------------------------------------------------------
__global__ void k_hist(const void* __restrict__ ei) {
    int e = blockIdx.x * blockDim.x + threadIdx.x;
    if (e < N_EDGES) atomicAdd(&g_cnt[edge_dst(ei, e)], 1);
}
__global__ void k_dinv() {
    int i = blockIdx.x * blockDim.x + threadIdx.x;
    if (i < N_NODES) g_dinv[i] = rsqrtf((float)g_cnt[i] + 1.0f);
}
__global__ __launch_bounds__(1024) void k_scan() {
    __shared__ int ssum[1024];
    const int t = threadIdx.x, CH = 49;
    int base = t * CH, s = 0;
    for (int j = 0; j < CH; j++) { int idx = base + j; if (idx < N_NODES) s += g_cnt[idx]; }
    ssum[t] = s; __syncthreads();
    for (int off = 1; off < 1024; off <<= 1) {
        int v = (t >= off) ? ssum[t - off] : 0;
        __syncthreads(); ssum[t] += v; __syncthreads();
    }
    int ex = (t == 0) ? 0 : ssum[t - 1];
    for (int j = 0; j < CH; j++) {
        int idx = base + j;
        if (idx < N_NODES) { g_rowptr[idx] = ex; ex += g_cnt[idx]; }
    }
    if (t == 1023) g_rowptr[N_NODES] = ssum[1023];
}
__global__ void k_place(const void* __restrict__ ei) {
    int e = blockIdx.x * blockDim.x + threadIdx.x;
    if (e < N_EDGES) {
        int s = edge_src(ei, e), d = edge_dst(ei, e);
        g_srcidx[g_rowptr[d] + atomicAdd(&g_fill[d], 1)] = s;
    }
}

// ---------------------------------------------------------------------------
// 3xTF32 mma.sync GEMM, occupancy-tuned:
//   block tile 64(M) x N, 256 thr = 8 warps in 2(M) x 4(N);
//   warp tile 32(M) x N/4 -> 32 accumulator regs (conv) instead of 64.
//   Fragment layouts identical to the numerically-validated R7 kernel.
// MODE 0: +bias+leaky -> g_h0 (encoder)   MODE 1: +bias -> ext (decoder)
// MODE 3: *dinv[m]    -> g_h1 (conv transform, prescaled)
// ---------------------------------------------------------------------------
template <int K, int N, int MODE, int SRC>
__global__ __launch_bounds__(256, 3)
void k_mma_gemm(const float* __restrict__ Aext, const float* __restrict__ W,
                const float* __restrict__ bias, float* __restrict__ Oext)
{
    constexpr int KC   = 16;            // K columns per staged chunk
    constexpr int KT   = KC / 8;        // k-tiles per chunk = 2
    constexpr int NTW  = N / 32;        // 8-wide n-tiles per warp (4 warps on N)
    constexpr int NC   = K / KC;        // chunks
    constexpr int B_F4 = (KC * N / 4) / 256;    // 2 (N=128) | 1 (N=64)

    __shared__ uint32_t sAh[64 * KC], sAl[64 * KC];    // 4KB each
    __shared__ uint32_t sBh[KC * N],  sBl[KC * N];     // 8KB each (N=128)

    const float* A   = (SRC == BUF_H0) ? g_h0 : Aext;
    float*       out = (MODE == 0) ? g_h0 : ((MODE == 3) ? g_h1 : Oext);

    const int tid    = threadIdx.x;
    const int wid    = tid >> 5;
    const int lane   = tid & 31;
    const int warp_m = wid >> 2;        // 0..1
    const int warp_n = wid & 3;         // 0..3
    const int gq     = lane >> 2;       // 0..7
    const int tq     = lane & 3;        // 0..3
    const int m0     = blockIdx.x * 64;

    float acc[2][NTW][4];
#pragma unroll
    for (int mt = 0; mt < 2; mt++)
#pragma unroll
        for (int nt = 0; nt < NTW; nt++)
#pragma unroll
            for (int j = 0; j < 4; j++) acc[mt][nt][j] = 0.0f;

    for (int kt0 = 0; kt0 < K; kt0 += KC) {
        // ---- stage A chunk: 64 rows x 16 cols = 1 float4/thread ----
        {
            int r = tid >> 2, q = tid & 3;   // row 0..63, float4-in-row 0..3
            int m = m0 + r;
            float4 v = (m < N_NODES) ? *(const float4*)&A[(size_t)m * K + kt0 + q * 4]
                                     : make_float4(0.f, 0.f, 0.f, 0.f);
            float vv[4] = {v.x, v.y, v.z, v.w};
            int rb = r >> 4, rr = r & 15;
#pragma unroll
            for (int c2 = 0; c2 < 4; c2++) {
                int kl = q * 4 + c2;
                uint32_t hi = f2tf32(vv[c2]);
                uint32_t lo = f2tf32(vv[c2] - __uint_as_float(hi));
                int kt = kl >> 3, t8 = kl & 7;
                int reg = ((rr >> 3) & 1) | ((t8 >> 2) << 1);
                int ln  = ((rr & 7) << 2) | (t8 & 3);
                int off = ((rb * KT + kt) * 32 + ln) * 4 + reg;
                sAh[off] = hi; sAl[off] = lo;
            }
        }
        // ---- stage B chunk: B[k][n] = W[kt0+k][n] ----
#pragma unroll
        for (int j = 0; j < B_F4; j++) {
            int f = tid + j * 256;
            int kl = f / (N / 4), q = f % (N / 4);
            float4 v = *(const float4*)&W[(size_t)(kt0 + kl) * N + q * 4];
            float vv[4] = {v.x, v.y, v.z, v.w};
            int kt = kl >> 3, t8 = kl & 7;
            int reg = (t8 >> 2) & 1;
#pragma unroll
            for (int c2 = 0; c2 < 4; c2++) {
                int n = q * 4 + c2;
                uint32_t hi = f2tf32(vv[c2]);
                uint32_t lo = f2tf32(vv[c2] - __uint_as_float(hi));
                int nt = n >> 3, g = n & 7;
                int ln  = (g << 2) | (t8 & 3);
                int off = ((nt * KT + kt) * 32 + ln) * 2 + reg;
                sBh[off] = hi; sBl[off] = lo;
            }
        }
        __syncthreads();

        // ---- MMA (fragment math identical to validated R7) ----
#pragma unroll
        for (int kt = 0; kt < KT; kt++) {
            uint4 ah[2], al[2];
#pragma unroll
            for (int mt = 0; mt < 2; mt++) {
                int rb = warp_m * 2 + mt;
                ah[mt] = *(const uint4*)&sAh[((rb * KT + kt) * 32 + lane) * 4];
                al[mt] = *(const uint4*)&sAl[((rb * KT + kt) * 32 + lane) * 4];
            }
#pragma unroll
            for (int ntl = 0; ntl < NTW; ntl++) {
                int nt = warp_n * NTW + ntl;
                uint2 bh = *(const uint2*)&sBh[((nt * KT + kt) * 32 + lane) * 2];
                uint2 bl = *(const uint2*)&sBl[((nt * KT + kt) * 32 + lane) * 2];
#pragma unroll
                for (int mt = 0; mt < 2; mt++) {
                    MMA_TF32(acc[mt][ntl], ah[mt], bh);
                    MMA_TF32(acc[mt][ntl], ah[mt], bl);
                    MMA_TF32(acc[mt][ntl], al[mt], bh);
                }
            }
        }
        __syncthreads();
    }

    // ---- epilogue: D frag c0/c1 -> row gq cols 2tq,2tq+1; c2/c3 -> row gq+8 ----
#pragma unroll
    for (int mt = 0; mt < 2; mt++) {
        int r0 = m0 + warp_m * 32 + mt * 16 + gq;
        int r1 = r0 + 8;
        float s0 = 1.0f, s1 = 1.0f;
        if (MODE == 3) {
            if (r0 < N_NODES) s0 = g_dinv[r0];
            if (r1 < N_NODES) s1 = g_dinv[r1];
        }
#pragma unroll
        for (int ntl = 0; ntl < NTW; ntl++) {
            int c0 = (warp_n * NTW + ntl) * 8 + 2 * tq;
            float b0 = 0.f, b1 = 0.f;
            if (MODE == 0 || MODE == 1) { b0 = bias[c0]; b1 = bias[c0 + 1]; }
            float d0 = acc[mt][ntl][0] + b0, d1 = acc[mt][ntl][1] + b1;
            float d2 = acc[mt][ntl][2] + b0, d3 = acc[mt][ntl][3] + b1;
            if (MODE == 0) {
                d0 = d0 > 0.f ? d0 : NEG_SLOPE * d0;
                d1 = d1 > 0.f ? d1 : NEG_SLOPE * d1;
                d2 = d2 > 0.f ? d2 : NEG_SLOPE * d2;
                d3 = d3 > 0.f ? d3 : NEG_SLOPE * d3;
            }
            if (MODE == 3) { d0 *= s0; d1 *= s0; d2 *= s1; d3 *= s1; }
            if (r0 < N_NODES) *(float2*)&out[(size_t)r0 * N + c0] = make_float2(d0, d1);
            if (r1 < N_NODES) *(float2*)&out[(size_t)r1 * N + c0] = make_float2(d2, d3);
        }
    }
}

// ---------------------------------------------------------------------------
// Aggregation gather: one warp per dst node; h1 prescaled by dinv.
// h0[d] = leaky(dinv[d]*(h1'[d] + sum h1'[src]) + bias)
// ---------------------------------------------------------------------------
__global__ __launch_bounds__(256)
void k_gather(const float* __restrict__ bias)
{
    int d    = (blockIdx.x * blockDim.x + threadIdx.x) >> 5;
    int lane = threadIdx.x & 31;
    if (d >= N_NODES) return;

    float dd  = g_dinv[d];
    int   beg = g_rowptr[d], end = g_rowptr[d + 1];

    float4 acc = *(const float4*)&g_h1[(size_t)d * HIDDEN + lane * 4];

    for (int j0 = beg; j0 < end; j0 += 32) {
        int n = min(32, end - j0);
        int myidx = (j0 + lane < end) ? g_srcidx[j0 + lane] : 0;
        for (int c = 0; c < n; c++) {
            int s = __shfl_sync(0xffffffffu, myidx, c);
            float4 u = *(const float4*)&g_h1[(size_t)s * HIDDEN + lane * 4];
            acc.x += u.x; acc.y += u.y; acc.z += u.z; acc.w += u.w;
        }
    }

    int c = lane * 4;
    acc.x = acc.x * dd + bias[c];     acc.y = acc.y * dd + bias[c + 1];
    acc.z = acc.z * dd + bias[c + 2]; acc.w = acc.w * dd + bias[c + 3];
    acc.x = acc.x > 0.f ? acc.x : NEG_SLOPE * acc.x;
    acc.y = acc.y > 0.f ? acc.y : NEG_SLOPE * acc.y;
    acc.z = acc.z > 0.f ? acc.z : NEG_SLOPE * acc.z;
    acc.w = acc.w > 0.f ? acc.w : NEG_SLOPE * acc.w;
    *(float4*)&g_h0[(size_t)d * HIDDEN + c] = acc;
}

// ---------------------------------------------------------------------------
// Launch
// ---------------------------------------------------------------------------
extern "C" void kernel_launch(void* const* d_in, const int* in_sizes, int n_in,
                              void* d_out, int out_size)
{
    const float* x      = (const float*)d_in[0];
    const void*  ei     = d_in[1];
    const float* enc_W  = (const float*)d_in[2];
    const float* enc_b  = (const float*)d_in[3];
    const float* conv_W = (const float*)d_in[4];
    const float* conv_b = (const float*)d_in[5];
    const float* dec_W  = (const float*)d_in[6];
    const float* dec_b  = (const float*)d_in[7];
    float*       out    = (float*)d_out;

    const int nodeBlocks = (N_NODES + 255) / 256;
    const int edgeBlocks = (N_EDGES + 255) / 256;
    const int mmaBlocks  = (N_NODES + 63) / 64;     // 782
    const int gathBlocks = (N_NODES * 32 + 255) / 256;

    k_init<<<nodeBlocks, 256>>>();
    k_detect<<<16, 256>>>((const unsigned*)ei);
    k_hist<<<edgeBlocks, 256>>>(ei);
    k_dinv<<<nodeBlocks, 256>>>();
    k_scan<<<1, 1024>>>();
    k_place<<<edgeBlocks, 256>>>(ei);

    // encoder: h0 = leaky(x @ enc_W + enc_b)
    k_mma_gemm<IN_DIM, HIDDEN, 0, BUF_EXT><<<mmaBlocks, 256>>>(x, enc_W, enc_b, nullptr);

    for (int l = 0; l < 2; l++) {
        const float* W = conv_W + (size_t)l * HIDDEN * HIDDEN;
        const float* b = conv_b + (size_t)l * HIDDEN;
        // g_h1 = (h0 @ W) * dinv
        k_mma_gemm<HIDDEN, HIDDEN, 3, BUF_H0><<<mmaBlocks, 256>>>(nullptr, W, nullptr, nullptr);
        // h0 = leaky(dinv * (h1'[self] + sum h1'[src]) + b)
        k_gather<<<gathBlocks, 256>>>(b);
    }

    // decoder: out = h0 @ dec_W + dec_b
    k_mma_gemm<HIDDEN, OUT_DIM, 1, BUF_H0><<<mmaBlocks, 256>>>(nullptr, dec_W, dec_b, out);
}

// round 12
// speedup vs baseline: 2.6053x; 2.6053x over previous
#include <cuda_runtime.h>
#include <cstdint>

#define N_NODES 50000
#define N_EDGES 800000
#define IN_DIM  256
#define HIDDEN  128
#define OUT_DIM 64
#define NEG_SLOPE 0.1f

// Scratch (device globals: allocation-free rule)
__device__ __align__(16) float g_h0[N_NODES * HIDDEN];  // activations
__device__ __align__(16) float g_h1[N_NODES * HIDDEN];  // transformed feats (prescaled)
__device__ float g_dinv[N_NODES];
__device__ int   g_cnt[N_NODES];
__device__ int   g_fill[N_NODES];
__device__ int   g_rowptr[N_NODES + 1];
__device__ int   g_srcidx[N_EDGES];
__device__ int   g_blksum[256];
__device__ int   g_blkoff[256];
__device__ int   g_is64;

#define BUF_EXT 0
#define BUF_H0  1
#define SCAN_BLOCKS 196   // ceil(50000/256)

// ---------------------------------------------------------------------------
// Init + dtype detection
// ---------------------------------------------------------------------------
__global__ void k_init() {
    int i = blockIdx.x * blockDim.x + threadIdx.x;
    if (i < N_NODES) { g_cnt[i] = 0; g_fill[i] = 0; }
    if (i == 0) g_is64 = 1;
}
// int64 edge_index with values < 50000 => every odd 32-bit word is zero.
__global__ void k_detect(const unsigned* __restrict__ e) {
    int i = blockIdx.x * blockDim.x + threadIdx.x;
    if (i < 4096) { if (e[2 * i + 1] != 0u) g_is64 = 0; }
}
__device__ __forceinline__ int edge_src(const void* ei, int e) {
    return g_is64 ? (int)((const long long*)ei)[e] : ((const int*)ei)[e];
}
__device__ __forceinline__ int edge_dst(const void* ei, int e) {
    return g_is64 ? (int)((const long long*)ei)[N_EDGES + e] : ((const int*)ei)[N_EDGES + e];
}

// ---------------------------------------------------------------------------
// CSR build: hist -> blocksum(+dinv) -> scan of block sums -> per-block scan -> place
// ---------------------------------------------------------------------------
__global__ void k_hist(const void* __restrict__ ei) {
    int e = blockIdx.x * blockDim.x + threadIdx.x;
    if (e < N_EDGES) atomicAdd(&g_cnt[edge_dst(ei, e)], 1);
}

__global__ __launch_bounds__(256) void k_blocksum() {
    __shared__ int s[256];
    int t = threadIdx.x;
    int i = blockIdx.x * 256 + t;
    int c = (i < N_NODES) ? g_cnt[i] : 0;
    if (i < N_NODES) g_dinv[i] = rsqrtf((float)c + 1.0f);   // +1 self loop
    s[t] = c; __syncthreads();
#pragma unroll
    for (int off = 128; off > 0; off >>= 1) {
        if (t < off) s[t] += s[t + off];
        __syncthreads();
    }
    if (t == 0) g_blksum[blockIdx.x] = s[0];
}

__global__ __launch_bounds__(256) void k_scanblk() {
    __shared__ int s[256];
    int t = threadIdx.x;
    int v = (t < SCAN_BLOCKS) ? g_blksum[t] : 0;
    s[t] = v; __syncthreads();
#pragma unroll
    for (int off = 1; off < 256; off <<= 1) {
        int u = (t >= off) ? s[t - off] : 0;
        __syncthreads(); s[t] += u; __syncthreads();
    }
    if (t < SCAN_BLOCKS) g_blkoff[t] = s[t] - v;            // exclusive
    if (t == 255) g_rowptr[N_NODES] = s[255];               // total
}

__global__ __launch_bounds__(256) void k_rowptr() {
    __shared__ int s[256];
    int t = threadIdx.x;
    int i = blockIdx.x * 256 + t;
    int c = (i < N_NODES) ? g_cnt[i] : 0;
    s[t] = c; __syncthreads();
#pragma unroll
    for (int off = 1; off < 256; off <<= 1) {
        int u = (t >= off) ? s[t - off] : 0;
        __syncthreads(); s[t] += u; __syncthreads();
    }
    if (i < N_NODES) g_rowptr[i] = g_blkoff[blockIdx.x] + s[t] - c;  // exclusive
}

__global__ void k_place(const void* __restrict__ ei) {
    int e = blockIdx.x * blockDim.x + threadIdx.x;
    if (e < N_EDGES) {
        int s = edge_src(ei, e), d = edge_dst(ei, e);
        g_srcidx[g_rowptr[d] + atomicAdd(&g_fill[d], 1)] = s;
    }
}

// ---------------------------------------------------------------------------
// Tiled fp32 GEMM (R4 skeleton, issue-optimized):  out[M,C] = A[M,K] @ W[K,C]
// TM=64, TK=64, 256 threads; k-unrolled x2 with float2 A loads:
//   per 2 k-steps: 2 LDS.128 (W) + RPT LDS.64 (A, broadcast) + 8*RPT FFMA
// MODE 0: +bias, leaky  (encoder: A=ext, out=g_h0)
// MODE 1: +bias         (decoder: A=g_h0, out=ext)
// MODE 3: *dinv[m]      (conv:    A=g_h0, out=g_h1 prescaled)
// ---------------------------------------------------------------------------
template <int K, int C, int MODE, int SRC>
__global__ __launch_bounds__(256)
void k_gemm(const float* __restrict__ Aext, const float* __restrict__ W,
            const float* __restrict__ bias, float* __restrict__ Oext)
{
    constexpr int TM = 64, TK = 64;
    constexpr int CG = C / 4;          // col groups (float4 wide): 32 | 16
    constexpr int RG = 256 / CG;       // row groups: 8 | 16
    constexpr int RPT = TM / RG;       // rows per thread: 8 | 4

    __shared__ float xs[TM][TK];       // 16 KB
    __shared__ float ws[TK][C];        // 32 KB (C=128) | 16 KB

    const float* A   = (SRC == BUF_H0) ? g_h0 : Aext;
    float*       out = (MODE == 0) ? g_h0 : ((MODE == 3) ? g_h1 : Oext);

    const int m0  = blockIdx.x * TM;
    const int tid = threadIdx.x;
    const int cg  = tid % CG;
    const int rg  = tid / CG;

    float acc[RPT][4];
#pragma unroll
    for (int r = 0; r < RPT; r++)
#pragma unroll
        for (int j = 0; j < 4; j++) acc[r][j] = 0.0f;

    for (int kt = 0; kt < K; kt += TK) {
        // stage A tile (zero-pad past M): 1024 float4, 4 per thread
#pragma unroll
        for (int i = tid; i < TM * TK / 4; i += 256) {
            int row = (i * 4) / TK, col = (i * 4) % TK;
            int m = m0 + row;
            float4 v = make_float4(0.f, 0.f, 0.f, 0.f);
            if (m < N_NODES)
                v = *(const float4*)&A[(size_t)m * K + kt + col];
            *(float4*)&xs[row][col] = v;
        }
        // stage W tile
#pragma unroll
        for (int i = tid; i < TK * C / 4; i += 256) {
            int row = (i * 4) / C, col = (i * 4) % C;
            *(float4*)&ws[row][col] = *(const float4*)&W[(size_t)(kt + row) * C + col];
        }
        __syncthreads();

#pragma unroll
        for (int k = 0; k < TK; k += 2) {
            float4 wv0 = *(const float4*)&ws[k][cg * 4];
            float4 wv1 = *(const float4*)&ws[k + 1][cg * 4];
#pragma unroll
            for (int r = 0; r < RPT; r++) {
                float2 a2 = *(const float2*)&xs[rg * RPT + r][k];
                acc[r][0] += a2.x * wv0.x; acc[r][1] += a2.x * wv0.y;
                acc[r][2] += a2.x * wv0.z; acc[r][3] += a2.x * wv0.w;
                acc[r][0] += a2.y * wv1.x; acc[r][1] += a2.y * wv1.y;
                acc[r][2] += a2.y * wv1.z; acc[r][3] += a2.y * wv1.w;
            }
        }
        __syncthreads();
    }

#pragma unroll
    for (int r = 0; r < RPT; r++) {
        int m = m0 + rg * RPT + r;
        if (m >= N_NODES) continue;
        int c = cg * 4;
        float4 v = make_float4(acc[r][0], acc[r][1], acc[r][2], acc[r][3]);
        if (MODE == 0 || MODE == 1) {
            v.x += bias[c]; v.y += bias[c + 1]; v.z += bias[c + 2]; v.w += bias[c + 3];
        }
        if (MODE == 0) {
            v.x = v.x > 0.f ? v.x : NEG_SLOPE * v.x;
            v.y = v.y > 0.f ? v.y : NEG_SLOPE * v.y;
            v.z = v.z > 0.f ? v.z : NEG_SLOPE * v.z;
            v.w = v.w > 0.f ? v.w : NEG_SLOPE * v.w;
        }
        if (MODE == 3) {
            float di = g_dinv[m];
            v.x *= di; v.y *= di; v.z *= di; v.w *= di;
        }
        *(float4*)&out[(size_t)m * C + c] = v;
    }
}

// ---------------------------------------------------------------------------
// Aggregation gather: one warp per dst node; h1 prescaled by dinv.
// h0[d] = leaky(dinv[d]*(h1'[d] + sum h1'[src]) + bias)
// src indices fetched 32-at-a-time per warp and broadcast via shfl.
// ---------------------------------------------------------------------------
__global__ __launch_bounds__(256)
void k_gather(const float* __restrict__ bias)
{
    int d    = (blockIdx.x * blockDim.x + threadIdx.x) >> 5;
    int lane = threadIdx.x & 31;
    if (d >= N_NODES) return;

    float dd  = g_dinv[d];
    int   beg = g_rowptr[d], end = g_rowptr[d + 1];

    float4 acc = *(const float4*)&g_h1[(size_t)d * HIDDEN + lane * 4];  // self

    for (int j0 = beg; j0 < end; j0 += 32) {
        int n = min(32, end - j0);
        int myidx = (j0 + lane < end) ? g_srcidx[j0 + lane] : 0;
        for (int c = 0; c < n; c++) {
            int s = __shfl_sync(0xffffffffu, myidx, c);
            float4 u = *(const float4*)&g_h1[(size_t)s * HIDDEN + lane * 4];
            acc.x += u.x; acc.y += u.y; acc.z += u.z; acc.w += u.w;
        }
    }

    int c = lane * 4;
    acc.x = acc.x * dd + bias[c];     acc.y = acc.y * dd + bias[c + 1];
    acc.z = acc.z * dd + bias[c + 2]; acc.w = acc.w * dd + bias[c + 3];
    acc.x = acc.x > 0.f ? acc.x : NEG_SLOPE * acc.x;
    acc.y = acc.y > 0.f ? acc.y : NEG_SLOPE * acc.y;
    acc.z = acc.z > 0.f ? acc.z : NEG_SLOPE * acc.z;
    acc.w = acc.w > 0.f ? acc.w : NEG_SLOPE * acc.w;
    *(float4*)&g_h0[(size_t)d * HIDDEN + c] = acc;
}

// ---------------------------------------------------------------------------
// Launch
// ---------------------------------------------------------------------------
extern "C" void kernel_launch(void* const* d_in, const int* in_sizes, int n_in,
                              void* d_out, int out_size)
{
    const float* x      = (const float*)d_in[0];
    const void*  ei     = d_in[1];                 // int32 or int64, detected
    const float* enc_W  = (const float*)d_in[2];
    const float* enc_b  = (const float*)d_in[3];
    const float* conv_W = (const float*)d_in[4];   // [2,128,128]
    const float* conv_b = (const float*)d_in[5];   // [2,128]
    const float* dec_W  = (const float*)d_in[6];
    const float* dec_b  = (const float*)d_in[7];
    float*       out    = (float*)d_out;

    const int nodeBlocks = (N_NODES + 255) / 256;       // 196
    const int edgeBlocks = (N_EDGES + 255) / 256;
    const int gemmBlocks = (N_NODES + 63) / 64;         // 782
    const int gathBlocks = (N_NODES * 32 + 255) / 256;

    k_init<<<nodeBlocks, 256>>>();
    k_detect<<<16, 256>>>((const unsigned*)ei);
    k_hist<<<edgeBlocks, 256>>>(ei);
    k_blocksum<<<SCAN_BLOCKS, 256>>>();
    k_scanblk<<<1, 256>>>();
    k_rowptr<<<SCAN_BLOCKS, 256>>>();
    k_place<<<edgeBlocks, 256>>>(ei);

    // encoder: h0 = leaky(x @ enc_W + enc_b)
    k_gemm<IN_DIM, HIDDEN, 0, BUF_EXT><<<gemmBlocks, 256>>>(x, enc_W, enc_b, nullptr);

    for (int l = 0; l < 2; l++) {
        const float* W = conv_W + (size_t)l * HIDDEN * HIDDEN;
        const float* b = conv_b + (size_t)l * HIDDEN;
        // g_h1 = (h0 @ W) * dinv   (prescaled transform)
        k_gemm<HIDDEN, HIDDEN, 3, BUF_H0><<<gemmBlocks, 256>>>(nullptr, W, nullptr, nullptr);
        // h0 = leaky(dinv * (h1'[self] + sum h1'[src]) + b)
        k_gather<<<gathBlocks, 256>>>(b);
    }

    // decoder: out = h0 @ dec_W + dec_b
    k_gemm<HIDDEN, OUT_DIM, 1, BUF_H0><<<gemmBlocks, 256>>>(nullptr, dec_W, dec_b, out);
}